// round 14
// baseline (speedup 1.0000x reference)
#include <cuda_runtime.h>
#include <cuda_bf16.h>
#include <math.h>

#define NB   16
#define LL   512
#define DM   512
#define DI   1024
#define DS   16
#define DTR  32
#define ROWS (NB*LL)   // 8192

// ---------------- scratch ----------------
__device__ float g_xmean_part[8][NB*DM];
__device__ float g_dA[NB*DM];
__device__ float g_dB[NB*DM];
__device__ float g_dC[NB*DM];
__device__ float g_dbl2[2][ROWS*64];   // xproj out fp32 per dir: [32,48)=B, [48,64)=C
__device__ __align__(16) __nv_bfloat16 g_dblb2[2][ROWS*DTR]; // dtraw bf16 (A of dt gemm)
__device__ __align__(16) __nv_bfloat16 g_dtb2[2][ROWS*DI];   // softplus dt bf16
__device__ __align__(16) __nv_bfloat16 g_yb2[2][ROWS*DI];    // scan out bf16 (bwd pre-flipped)
__device__ __align__(16) __nv_bfloat16 g_xzb[ROWS*2*DI];     // W_in out bf16
__device__ __align__(16) __nv_bfloat16 g_xcb2[2][ROWS*DI];   // conv out bf16; [0] reused as gated ys
__device__ __align__(16) __nv_bfloat16 g_hnb[ROWS*DM];
__device__ __align__(16) __nv_bfloat16 g_wb[1769472];

#define OFF_WIN   0
#define OFF_WOUT  1048576
#define OFF_XPF   1572864
#define OFF_XPB   1638400
#define OFF_DTWF  1703936
#define OFF_DTWB  1736704

// ---------------- helpers ----------------
__device__ __forceinline__ float geluf(float x){
    return 0.5f*x*(1.0f + erff(x*0.70710678118654752f));
}
__device__ __forceinline__ float siluf(float x){
    return x / (1.0f + __expf(-x));
}
__device__ __forceinline__ float softplusf(float x){
    return (x > 20.0f) ? x : __logf(1.0f + __expf(x));
}
__device__ __forceinline__ void mma_bf16(float* d, const unsigned* a, const unsigned* b){
    asm volatile("mma.sync.aligned.m16n8k16.row.col.f32.bf16.bf16.f32 "
        "{%0,%1,%2,%3}, {%4,%5,%6,%7}, {%8,%9}, {%0,%1,%2,%3};"
        : "+f"(d[0]), "+f"(d[1]), "+f"(d[2]), "+f"(d[3])
        : "r"(a[0]), "r"(a[1]), "r"(a[2]), "r"(a[3]), "r"(b[0]), "r"(b[1]));
}
__device__ __forceinline__ float warp_dot(const float* __restrict__ w,
                                          const float* __restrict__ sx, int K, int lane){
    float s = 0.f;
    for (int k = lane*4; k < K; k += 128){
        float4 a = *(const float4*)&w[k];
        float4 b = *(const float4*)&sx[k];
        s += a.x*b.x + a.y*b.y + a.z*b.z + a.w*b.w;
    }
    #pragma unroll
    for (int o = 16; o; o >>= 1) s += __shfl_xor_sync(0xffffffffu, s, o);
    return s;
}

// ---------------- K1: fused weight-convert + mean partials (independent work) ----
__global__ void __launch_bounds__(256) k_init(
    const float* __restrict__ W_in, const float* __restrict__ W_out,
    const float* __restrict__ xpf,  const float* __restrict__ xpb,
    const float* __restrict__ dtf,  const float* __restrict__ dtb_,
    const float* __restrict__ x,    __nv_bfloat16* __restrict__ wb)
{
    int b = blockIdx.x, tid = threadIdx.x;
    if (b < 6144){
        int i = b*256 + tid;                 // [0, 1572864)
        if (i < 2*DI*DM) wb[OFF_WIN + i] = __float2bfloat16(W_in[i]);
        else wb[OFF_WOUT + i - 2*DI*DM] = __float2bfloat16(W_out[i - 2*DI*DM]);
    } else if (b < 6912){
        int i = (b - 6144)*256 + tid;        // [0, 196608)
        if (i < 65536) wb[OFF_XPF + i] = __float2bfloat16(xpf[i]);
        else if (i < 131072) wb[OFF_XPB + i-65536] = __float2bfloat16(xpb[i-65536]);
        else if (i < 163840) wb[OFF_DTWF + i-131072] = __float2bfloat16(dtf[i-131072]);
        else wb[OFF_DTWB + i-163840] = __float2bfloat16(dtb_[i-163840]);
    } else {
        int idx = b - 6912;                  // [0, 128): mean partials
        int n = idx >> 3, p = idx & 7;
        const float* px = x + ((size_t)n*LL + p*64)*DM;
        for (int j = tid; j < DM; j += 256){
            float s = 0.f;
            #pragma unroll 8
            for (int t = 0; t < 64; t++) s += px[(size_t)t*DM + j];
            g_xmean_part[p][n*DM + j] = s;
        }
    }
}

// ---------------- K2: fused conditioning, warp-per-output (16 x 1024) ------------
__global__ void __launch_bounds__(1024) k_cond(
    const float* __restrict__ Wgf, const float* __restrict__ bgf,
    const float* __restrict__ emb, const int* __restrict__ sid,
    const float* __restrict__ W1,  const float* __restrict__ b1,
    const float* __restrict__ W2,  const float* __restrict__ b2,
    const float* __restrict__ W3,  const float* __restrict__ b3,
    const float* __restrict__ lng, const float* __restrict__ lnb)
{
    __shared__ __align__(16) float sx[DM];
    __shared__ __align__(16) float sc[256];
    __shared__ __align__(16) float sh[DM];
    __shared__ __align__(16) float sh2[DM];
    __shared__ __align__(16) float so[3*DM];
    __shared__ float r1[32], r2[32];
    int n = blockIdx.x, tid = threadIdx.x;
    int wid = tid >> 5, lane = tid & 31;

    if (tid < DM){
        float s = 0.f;
        #pragma unroll
        for (int p = 0; p < 8; p++) s += g_xmean_part[p][n*DM + tid];
        sx[tid] = s * (1.0f/LL);
    }
    if (tid >= 128 && tid < 256) sc[tid] = emb[sid[0]*128 + (tid - 128)];
    __syncthreads();
    // gf: 128 outputs, 4 per warp
    #pragma unroll
    for (int k = 0; k < 4; k++){
        int j = wid*4 + k;
        float s = warp_dot(Wgf + (size_t)j*DM, sx, DM, lane);
        if (lane == 0) sc[j] = geluf(s + bgf[j]);
    }
    __syncthreads();
    // h1: 512 outputs, 16 per warp
    #pragma unroll
    for (int k = 0; k < 16; k++){
        int j = wid*16 + k;
        float s = warp_dot(W1 + (size_t)j*256, sc, 256, lane);
        if (lane == 0) sh[j] = geluf(s + b1[j]);
    }
    __syncthreads();
    // h2: 512 outputs
    #pragma unroll
    for (int k = 0; k < 16; k++){
        int j = wid*16 + k;
        float s = warp_dot(W2 + (size_t)j*DM, sh, DM, lane);
        if (lane == 0) sh2[j] = geluf(s + b2[j]);
    }
    __syncthreads();
    // off: 1536 outputs, 48 per warp
    #pragma unroll
    for (int k = 0; k < 48; k++){
        int j = k*32 + wid;
        float s = warp_dot(W3 + (size_t)j*DM, sh2, DM, lane);
        if (lane == 0) so[j] = s + b3[j];
    }
    __syncthreads();
    // per-chunk LayerNorm
    float scv = 0.9f - 0.3f*(float)sid[0];
    for (int c = 0; c < 3; c++){
        float v = (tid < DM) ? so[c*DM + tid] : 0.f;
        float s1 = v, s2 = v*v;
        #pragma unroll
        for (int o = 16; o > 0; o >>= 1){
            s1 += __shfl_xor_sync(0xffffffffu, s1, o);
            s2 += __shfl_xor_sync(0xffffffffu, s2, o);
        }
        if (lane == 0){ r1[wid] = s1; r2[wid] = s2; }
        __syncthreads();
        if (tid < 32){
            float a = r1[tid], b = r2[tid];
            #pragma unroll
            for (int o = 16; o > 0; o >>= 1){
                a += __shfl_xor_sync(0xffffffffu, a, o);
                b += __shfl_xor_sync(0xffffffffu, b, o);
            }
            if (tid == 0){ r1[0] = a; r2[0] = b; }
        }
        __syncthreads();
        float mu  = r1[0] * (1.0f/DM);
        float var = r2[0] * (1.0f/DM) - mu*mu;
        if (tid < DM){
            float w = (v - mu) * rsqrtf(var + 1e-5f) * lng[tid] + lnb[tid];
            if (c == 0)      g_dA[n*DM + tid] = w * scv;
            else if (c == 1) g_dB[n*DM + tid] = w;
            else             g_dC[n*DM + tid] = w;
        }
        __syncthreads();
    }
}

// ---------------- residual + rmsnorm ----------------
__global__ void k_res(const float* __restrict__ x, const float* __restrict__ hinit,
                      const float* __restrict__ rmsw, float* __restrict__ resid){
    __shared__ float red[16];
    int m = blockIdx.x, j = threadIdx.x;
    int n = m >> 9, t = m & 511;
    float v = x[(size_t)m*DM + j] + g_dB[n*DM + j];
    if (t == 0) v += hinit[n*DM + j];
    resid[(size_t)m*DM + j] = v;
    float s2 = v*v;
    #pragma unroll
    for (int o = 16; o > 0; o >>= 1) s2 += __shfl_xor_sync(0xffffffffu, s2, o);
    int wid = j >> 5, ln = j & 31;
    if (ln == 0) red[wid] = s2;
    __syncthreads();
    if (j < 16){
        float a = red[j];
        #pragma unroll
        for (int o = 8; o > 0; o >>= 1) a += __shfl_xor_sync(0x0000ffffu, a, o);
        if (j == 0) red[0] = a;
    }
    __syncthreads();
    float rs = rsqrtf(red[0]*(1.0f/DM) + 1e-5f);
    g_hnb[(size_t)m*DM + j] = __float2bfloat16(v * rs * rmsw[j]);
}

// ---------------- bf16 GEMM, 2-stage cp.async, dynamic smem, dir-batched ---------
// EPI: 2 fp32 + bf16 copy col<32 (pitch DTR); 4 final fusion; 5 bf16 store;
//      6 softplus(+bias) -> bf16 store.
struct GemmArgs {
    const __nv_bfloat16* A;
    const __nv_bfloat16* B;
    float* C;
    __nv_bfloat16* Cb;
    const float* bias;
};
template<int BM,int BN,int BK,int WGM,int WGN,int EPI>
__global__ void __launch_bounds__(256) gemm_bf16(
    GemmArgs a0, GemmArgs a1,
    int lda, int ldb, int ldc, int K,
    const float* __restrict__ resid, const float* __restrict__ dAp,
    const float* __restrict__ dCp, const float* __restrict__ resw,
    float* __restrict__ hfin)
{
    constexpr int PITCH = BK + 8;
    constexpr int WM = BM/WGM, WN = BN/WGN;
    constexpr int MF = WM/16, NF = WN/8;
    extern __shared__ __align__(16) __nv_bfloat16 smem[];
    __nv_bfloat16* sA = smem;                       // [2][BM*PITCH]
    __nv_bfloat16* sB = smem + 2*BM*PITCH;          // [2][BN*PITCH]
    GemmArgs ga = (blockIdx.z == 0) ? a0 : a1;
    const __nv_bfloat16* A = ga.A;
    const __nv_bfloat16* B = ga.B;
    int tid = threadIdx.x;
    int lane = tid & 31, wid = tid >> 5;
    int wm = wid % WGM, wn = wid / WGM;
    int bm0 = blockIdx.y*BM, bn0 = blockIdx.x*BN;

    float acc[MF][NF][4];
    #pragma unroll
    for (int i = 0; i < MF; i++)
        #pragma unroll
        for (int j = 0; j < NF; j++)
            #pragma unroll
            for (int r = 0; r < 4; r++) acc[i][j][r] = 0.f;

    auto load_tile = [&](int st, int k0){
        constexpr int CA = BM*BK/8;
        __nv_bfloat16* dA_ = sA + st*BM*PITCH;
        #pragma unroll
        for (int c = tid; c < CA; c += 256){
            int r = c/(BK/8), c8 = c%(BK/8);
            const void* src = &A[(size_t)(bm0+r)*lda + k0 + c8*8];
            unsigned dst = (unsigned)__cvta_generic_to_shared(&dA_[r*PITCH + c8*8]);
            asm volatile("cp.async.cg.shared.global [%0], [%1], 16;" :: "r"(dst), "l"(src));
        }
        constexpr int CB = BN*BK/8;
        __nv_bfloat16* dB_ = sB + st*BN*PITCH;
        #pragma unroll
        for (int c = tid; c < CB; c += 256){
            int r = c/(BK/8), c8 = c%(BK/8);
            const void* src = &B[(size_t)(bn0+r)*ldb + k0 + c8*8];
            unsigned dst = (unsigned)__cvta_generic_to_shared(&dB_[r*PITCH + c8*8]);
            asm volatile("cp.async.cg.shared.global [%0], [%1], 16;" :: "r"(dst), "l"(src));
        }
    };

    const int KT = K / BK;
    load_tile(0, 0);
    asm volatile("cp.async.commit_group;");
    for (int kt = 0; kt < KT; kt++){
        if (kt + 1 < KT) load_tile((kt+1)&1, (kt+1)*BK);
        asm volatile("cp.async.commit_group;");
        asm volatile("cp.async.wait_group 1;");
        __syncthreads();
        int st = kt & 1;
        const __nv_bfloat16* tA = sA + st*BM*PITCH;
        const __nv_bfloat16* tB = sB + st*BN*PITCH;
        #pragma unroll
        for (int kc = 0; kc < BK; kc += 16){
            unsigned af[MF][4], bf[NF][2];
            #pragma unroll
            for (int mf = 0; mf < MF; mf++){
                unsigned addr = (unsigned)__cvta_generic_to_shared(
                    &tA[(wm*WM + mf*16 + (lane&15))*PITCH + kc + (lane>>4)*8]);
                asm volatile("ldmatrix.sync.aligned.m8n8.x4.shared.b16 {%0,%1,%2,%3}, [%4];"
                    : "=r"(af[mf][0]),"=r"(af[mf][1]),"=r"(af[mf][2]),"=r"(af[mf][3])
                    : "r"(addr));
            }
            #pragma unroll
            for (int nf = 0; nf < NF; nf++){
                unsigned addr = (unsigned)__cvta_generic_to_shared(
                    &tB[(wn*WN + nf*8 + (lane&7))*PITCH + kc + ((lane>>3)&1)*8]);
                asm volatile("ldmatrix.sync.aligned.m8n8.x2.shared.b16 {%0,%1}, [%2];"
                    : "=r"(bf[nf][0]),"=r"(bf[nf][1]) : "r"(addr));
            }
            #pragma unroll
            for (int mf = 0; mf < MF; mf++)
                #pragma unroll
                for (int nf = 0; nf < NF; nf++)
                    mma_bf16(acc[mf][nf], af[mf], bf[nf]);
        }
        __syncthreads();
    }

    float rw = 0.f;
    if (EPI == 4) rw = resw[0];
    #pragma unroll
    for (int mf = 0; mf < MF; mf++){
        int row0 = bm0 + wm*WM + mf*16 + (lane >> 2);
        #pragma unroll
        for (int nf = 0; nf < NF; nf++){
            int col = bn0 + wn*WN + nf*8 + (lane & 3)*2;
            float v[4] = {acc[mf][nf][0], acc[mf][nf][1], acc[mf][nf][2], acc[mf][nf][3]};
            if (EPI == 6){
                float bA = ga.bias[col], bB = ga.bias[col+1];
                v[0] = softplusf(v[0]+bA); v[1] = softplusf(v[1]+bB);
                v[2] = softplusf(v[2]+bA); v[3] = softplusf(v[3]+bB);
            }
            if (EPI == 4){
                #pragma unroll
                for (int h = 0; h < 2; h++){
                    int row = row0 + h*8;
                    int n = row >> 9, t = row & 511;
                    float A0 = 1.0f + 0.1f*dAp[n*DM + col];
                    float A1 = 1.0f + 0.1f*dAp[n*DM + col+1];
                    float c0 = 0.1f*dCp[n*DM + col];
                    float c1 = 0.1f*dCp[n*DM + col+1];
                    float r0 = rw*resid[(size_t)row*DM + col];
                    float r1 = rw*resid[(size_t)row*DM + col+1];
                    v[2*h]   = v[2*h]*A0 + c0 + r0;
                    v[2*h+1] = v[2*h+1]*A1 + c1 + r1;
                    if (t == LL-1){
                        hfin[n*DM + col]   = v[2*h];
                        hfin[n*DM + col+1] = v[2*h+1];
                    }
                }
            }
            if (EPI == 5 || EPI == 6){
                __nv_bfloat162 p0, p1;
                p0.x = __float2bfloat16(v[0]); p0.y = __float2bfloat16(v[1]);
                p1.x = __float2bfloat16(v[2]); p1.y = __float2bfloat16(v[3]);
                *(__nv_bfloat162*)&ga.Cb[(size_t)row0*ldc + col]     = p0;
                *(__nv_bfloat162*)&ga.Cb[(size_t)(row0+8)*ldc + col] = p1;
            } else {
                *(float2*)&ga.C[(size_t)row0*ldc + col]     = make_float2(v[0], v[1]);
                *(float2*)&ga.C[(size_t)(row0+8)*ldc + col] = make_float2(v[2], v[3]);
                if (EPI == 2 && col < 32){
                    ga.Cb[row0*DTR + col]       = __float2bfloat16(v[0]);
                    ga.Cb[row0*DTR + col+1]     = __float2bfloat16(v[1]);
                    ga.Cb[(row0+8)*DTR + col]   = __float2bfloat16(v[2]);
                    ga.Cb[(row0+8)*DTR + col+1] = __float2bfloat16(v[3]);
                }
            }
        }
    }
}

// ---------------- depthwise conv + silu, both dirs (blockIdx.z) ----------------
__global__ void k_conv(const float* __restrict__ cwf, const float* __restrict__ cbf,
                       const float* __restrict__ cwb, const float* __restrict__ cbb){
    int dir = blockIdx.z;
    const float* cw = dir ? cwb : cwf;
    const float* cb = dir ? cbb : cbf;
    int blk = blockIdx.x;                   // (NB*64, 4, 2) x 256
    int n = blk >> 6, tt = (blk & 63)*8;
    int d = blockIdx.y*256 + threadIdx.x;
    const float* w = cw + d*4;
    float w0 = w[0], w1 = w[1], w2 = w[2], w3 = w[3];
    float bias = cb[d];
    float xv[11];
    #pragma unroll
    for (int j = 0; j < 11; j++){
        int tau = tt - 3 + j;
        if (tau >= 0){
            int src = dir ? (LL-1-tau) : tau;
            xv[j] = __bfloat162float(g_xzb[(size_t)(n*LL + src)*(2*DI) + d]);
        } else xv[j] = 0.f;
    }
    __nv_bfloat16* dst = g_xcb2[dir];
    #pragma unroll
    for (int i = 0; i < 8; i++){
        float s = bias + w0*xv[i] + w1*xv[i+1] + w2*xv[i+2] + w3*xv[i+3];
        size_t m = (size_t)(n*LL + tt + i);
        dst[m*DI + d] = __float2bfloat16(siluf(s));
    }
}

// ---------------- selective scan, both dirs in one launch (blockIdx.z) ----------
__global__ void __launch_bounds__(256) k_scan2(
    const float* __restrict__ Af, const float* __restrict__ Df,
    const float* __restrict__ Ab, const float* __restrict__ Db)
{
    int dir = blockIdx.z;
    const float* Alog = dir ? Ab : Af;
    const float* Dp   = dir ? Db : Df;
    const __nv_bfloat16* xu  = g_xcb2[dir];
    const __nv_bfloat16* dtp = g_dtb2[dir];
    const float* dbl = g_dbl2[dir];
    __nv_bfloat16* y = g_yb2[dir];

    int n  = blockIdx.y;
    int ch = blockIdx.x*64 + (threadIdx.x >> 2);
    int s0 = (threadIdx.x & 3) * 4;
    bool lead = (threadIdx.x & 3) == 0;
    float A2[4];
    #pragma unroll
    for (int i = 0; i < 4; i++)
        A2[i] = -__expf(Alog[ch*DS + s0 + i]) * 1.44269504088896f;
    float Dv = Dp[ch];
    float h0=0.f,h1=0.f,h2=0.f,h3=0.f;
    size_t base = (size_t)n*LL;

    float pu[8], pd[8]; float4 pB[8], pC[8];
    #pragma unroll
    for (int i = 0; i < 8; i++){
        size_t r = base + i;
        pu[i] = __bfloat162float(xu[r*DI + ch]);
        pd[i] = __bfloat162float(dtp[r*DI + ch]);
        pB[i] = *(const float4*)&dbl[r*64 + DTR + s0];
        pC[i] = *(const float4*)&dbl[r*64 + DTR + DS + s0];
    }

    for (int t0 = 0; t0 < LL; t0 += 8){
        #pragma unroll
        for (int i = 0; i < 8; i++){
            int t = t0 + i;
            float u = pu[i], dv = pd[i];
            float4 Bv = pB[i], Cv = pC[i];
            int tn = t + 8;
            if (tn < LL){
                size_t r = base + tn;
                pu[i] = __bfloat162float(xu[r*DI + ch]);
                pd[i] = __bfloat162float(dtp[r*DI + ch]);
                pB[i] = *(const float4*)&dbl[r*64 + DTR + s0];
                pC[i] = *(const float4*)&dbl[r*64 + DTR + DS + s0];
            }
            float du = dv*u;
            h0 = exp2f(dv*A2[0])*h0 + du*Bv.x;
            h1 = exp2f(dv*A2[1])*h1 + du*Bv.y;
            h2 = exp2f(dv*A2[2])*h2 + du*Bv.z;
            h3 = exp2f(dv*A2[3])*h3 + du*Bv.w;
            float acc = h0*Cv.x + h1*Cv.y + h2*Cv.z + h3*Cv.w;
            acc += __shfl_xor_sync(0xffffffffu, acc, 1);
            acc += __shfl_xor_sync(0xffffffffu, acc, 2);
            if (lead){
                int tout = dir ? (LL-1-t) : t;
                y[(base + tout)*DI + ch] = __float2bfloat16(acc + u*Dv);
            }
        }
    }
}

// ---------------- ys = (y_f + y_b) * silu(z) -> bf16 ----------------
__global__ void k_ymul(){
    size_t m = blockIdx.x;
    int d = threadIdx.x*4;
    const __nv_bfloat162* y0p = (const __nv_bfloat162*)&g_yb2[0][m*DI + d];
    const __nv_bfloat162* y1p = (const __nv_bfloat162*)&g_yb2[1][m*DI + d];
    const __nv_bfloat162* zp  = (const __nv_bfloat162*)&g_xzb[m*(2*DI) + DI + d];
    __nv_bfloat162 o[2];
    #pragma unroll
    for (int q = 0; q < 2; q++){
        __nv_bfloat162 y0 = y0p[q], y1 = y1p[q], z = zp[q];
        float a = __bfloat162float(y0.x) + __bfloat162float(y1.x);
        float b = __bfloat162float(y0.y) + __bfloat162float(y1.y);
        o[q].x = __float2bfloat16(a * siluf(__bfloat162float(z.x)));
        o[q].y = __float2bfloat16(b * siluf(__bfloat162float(z.y)));
    }
    __nv_bfloat162* op = (__nv_bfloat162*)&g_xcb2[0][m*DI + d];
    op[0] = o[0]; op[1] = o[1];
}

// ---------------- launch ----------------
extern "C" void kernel_launch(void* const* d_in, const int* in_sizes, int n_in,
                              void* d_out, int out_size)
{
    const float* x      = (const float*)d_in[0];
    const int*   sid    = (const int*)  d_in[1];
    const float* h_init = (const float*)d_in[2];
    const float* W_gf   = (const float*)d_in[3];
    const float* b_gf   = (const float*)d_in[4];
    const float* emb    = (const float*)d_in[5];
    const float* W1     = (const float*)d_in[6];
    const float* b1     = (const float*)d_in[7];
    const float* W2     = (const float*)d_in[8];
    const float* b2     = (const float*)d_in[9];
    const float* W3     = (const float*)d_in[10];
    const float* b3     = (const float*)d_in[11];
    const float* ln_g   = (const float*)d_in[12];
    const float* ln_b   = (const float*)d_in[13];
    const float* rms_w  = (const float*)d_in[14];
    const float* W_in   = (const float*)d_in[15];
    const float* W_out  = (const float*)d_in[16];
    const float* res_w  = (const float*)d_in[17];
    const float* convw_f= (const float*)d_in[18];
    const float* convb_f= (const float*)d_in[19];
    const float* xproj_f= (const float*)d_in[20];
    const float* dtw_f  = (const float*)d_in[21];
    const float* dtb_f  = (const float*)d_in[22];
    const float* Alog_f = (const float*)d_in[23];
    const float* D_f    = (const float*)d_in[24];
    const float* convw_b= (const float*)d_in[25];
    const float* convb_b= (const float*)d_in[26];
    const float* xproj_b= (const float*)d_in[27];
    const float* dtw_b  = (const float*)d_in[28];
    const float* dtb_b  = (const float*)d_in[29];
    const float* Alog_b = (const float*)d_in[30];
    const float* D_b    = (const float*)d_in[31];

    float* out   = (float*)d_out;
    float* resid = out + (size_t)ROWS*DM;
    float* hfin  = out + 2*(size_t)ROWS*DM;

    float *p_dbl0, *p_dbl1, *p_dA, *p_dC;
    __nv_bfloat16 *p_hnb, *p_xzb, *p_xcb0, *p_xcb1, *p_dblb0, *p_dblb1, *p_dtb0, *p_dtb1, *p_wb;
    cudaGetSymbolAddress((void**)&p_dbl0, g_dbl2);
    p_dbl1 = p_dbl0 + (size_t)ROWS*64;
    cudaGetSymbolAddress((void**)&p_dA,   g_dA);
    cudaGetSymbolAddress((void**)&p_dC,   g_dC);
    cudaGetSymbolAddress((void**)&p_hnb,  g_hnb);
    cudaGetSymbolAddress((void**)&p_xzb,  g_xzb);
    cudaGetSymbolAddress((void**)&p_xcb0, g_xcb2);
    p_xcb1 = p_xcb0 + (size_t)ROWS*DI;
    cudaGetSymbolAddress((void**)&p_dblb0,g_dblb2);
    p_dblb1 = p_dblb0 + (size_t)ROWS*DTR;
    cudaGetSymbolAddress((void**)&p_dtb0, g_dtb2);
    p_dtb1 = p_dtb0 + (size_t)ROWS*DI;
    cudaGetSymbolAddress((void**)&p_wb,   g_wb);

    // dynamic smem sizes: 2*(BM+BN)*(BK+8)*2 bytes
    const int SM_BK64_128 = 2*(128+128)*72*2;  // 73728
    const int SM_BK64_64  = 2*(64+64)*72*2;    // 36864
    const int SM_BK32_128 = 2*(128+128)*40*2;  // 40960
    cudaFuncSetAttribute(gemm_bf16<128,128,64,2,4,5>,
        cudaFuncAttributeMaxDynamicSharedMemorySize, SM_BK64_128);
    cudaFuncSetAttribute(gemm_bf16<128,128,64,2,4,4>,
        cudaFuncAttributeMaxDynamicSharedMemorySize, SM_BK64_128);

    // (1) fused convert + mean partials
    k_init<<<7040, 256>>>(W_in, W_out, xproj_f, xproj_b, dtw_f, dtw_b, x, p_wb);

    // (2) fused conditioning (warp-per-output)
    k_cond<<<NB, 1024>>>(W_gf, b_gf, emb, sid, W1, b1, W2, b2, W3, b3, ln_g, ln_b);

    // (3) residual + rmsnorm
    k_res<<<ROWS, DM>>>(x, h_init, rms_w, resid);

    // (4) xz = hn @ W_in.T -> bf16  (BK=64)  <-- profiled launch
    {
        GemmArgs a0 = { p_hnb, p_wb + OFF_WIN, nullptr, p_xzb, nullptr };
        gemm_bf16<128,128,64,2,4,5><<<dim3(16, 64, 1), 256, SM_BK64_128>>>(
            a0, a0, DM, DM, 2*DI, DM, nullptr, nullptr, nullptr, nullptr, nullptr);
    }

    // (5) conv both dirs
    k_conv<<<dim3(NB*64, 4, 2), 256>>>(convw_f, convb_f, convw_b, convb_b);

    // (6) xproj both dirs (fp32 B/C + bf16 dtraw), BK=64
    {
        GemmArgs a0 = { p_xcb0, p_wb + OFF_XPF, p_dbl0, p_dblb0, nullptr };
        GemmArgs a1 = { p_xcb1, p_wb + OFF_XPB, p_dbl1, p_dblb1, nullptr };
        gemm_bf16<64,64,64,2,4,2><<<dim3(1, 128, 2), 256, SM_BK64_64>>>(
            a0, a1, DI, DI, 64, DI, nullptr, nullptr, nullptr, nullptr, nullptr);
    }

    // (7) dt both dirs -> softplus -> bf16 (K=32, single tile, BK=32)
    {
        GemmArgs a0 = { p_dblb0, p_wb + OFF_DTWF, nullptr, p_dtb0, dtb_f };
        GemmArgs a1 = { p_dblb1, p_wb + OFF_DTWB, nullptr, p_dtb1, dtb_b };
        gemm_bf16<128,128,32,2,4,6><<<dim3(8, 64, 2), 256, SM_BK32_128>>>(
            a0, a1, DTR, DTR, DI, DTR, nullptr, nullptr, nullptr, nullptr, nullptr);
    }

    // (8) scan both dirs concurrently
    k_scan2<<<dim3(16, NB, 2), 256>>>(Alog_f, D_f, Alog_b, D_b);

    // (9) gating
    k_ymul<<<ROWS, 256>>>();

    // (10) W_out gemm with fused final epilogue  (BK=64)
    {
        GemmArgs a0 = { p_xcb0, p_wb + OFF_WOUT, out, nullptr, nullptr };
        gemm_bf16<128,128,64,2,4,4><<<dim3(4, 64, 1), 256, SM_BK64_128>>>(
            a0, a0, DI, DI, DM, DI, resid, p_dA, p_dC, res_w, hfin);
    }
}

// round 15
// speedup vs baseline: 1.1766x; 1.1766x over previous
#include <cuda_runtime.h>
#include <cuda_bf16.h>
#include <math.h>

#define NB   16
#define LL   512
#define DM   512
#define DI   1024
#define DS   16
#define DTR  32
#define ROWS (NB*LL)   // 8192

// ---------------- scratch ----------------
__device__ float g_xmean_part[8][NB*DM];
__device__ float g_gf[NB*128];
__device__ float g_h1[NB*DM];
__device__ float g_h2[NB*DM];
__device__ float g_off[NB*3*DM];
__device__ float g_dA[NB*DM];
__device__ float g_dB[NB*DM];
__device__ float g_dC[NB*DM];
__device__ float g_dbl2[2][ROWS*64];   // xproj out fp32 per dir: [32,48)=B, [48,64)=C
__device__ __align__(16) __nv_bfloat16 g_dblb2[2][ROWS*DTR]; // dtraw bf16 (A of dt gemm)
__device__ __align__(16) __nv_bfloat16 g_dtb2[2][ROWS*DI];   // softplus dt bf16
__device__ __align__(16) __nv_bfloat16 g_yb2[2][ROWS*DI];    // scan out bf16 (bwd pre-flipped)
__device__ __align__(16) __nv_bfloat16 g_xzb[ROWS*2*DI];     // W_in out bf16
__device__ __align__(16) __nv_bfloat16 g_xcb2[2][ROWS*DI];   // conv out bf16; [0] reused as gated ys
__device__ __align__(16) __nv_bfloat16 g_hnb[ROWS*DM];
__device__ __align__(16) __nv_bfloat16 g_wb[1769472];

#define OFF_WIN   0
#define OFF_WOUT  1048576
#define OFF_XPF   1572864
#define OFF_XPB   1638400
#define OFF_DTWF  1703936
#define OFF_DTWB  1736704

// ---------------- helpers ----------------
__device__ __forceinline__ float geluf(float x){
    return 0.5f*x*(1.0f + erff(x*0.70710678118654752f));
}
__device__ __forceinline__ float siluf(float x){
    return x / (1.0f + __expf(-x));
}
__device__ __forceinline__ float softplusf(float x){
    return (x > 20.0f) ? x : __logf(1.0f + __expf(x));
}
__device__ __forceinline__ void mma_bf16(float* d, const unsigned* a, const unsigned* b){
    asm volatile("mma.sync.aligned.m16n8k16.row.col.f32.bf16.bf16.f32 "
        "{%0,%1,%2,%3}, {%4,%5,%6,%7}, {%8,%9}, {%0,%1,%2,%3};"
        : "+f"(d[0]), "+f"(d[1]), "+f"(d[2]), "+f"(d[3])
        : "r"(a[0]), "r"(a[1]), "r"(a[2]), "r"(a[3]), "r"(b[0]), "r"(b[1]));
}
__device__ __forceinline__ float warp_dot(const float* __restrict__ w,
                                          const float* __restrict__ sx, int K, int lane){
    float s = 0.f;
    for (int k = lane*4; k < K; k += 128){
        float4 a = *(const float4*)&w[k];
        float4 b = *(const float4*)&sx[k];
        s += a.x*b.x + a.y*b.y + a.z*b.z + a.w*b.w;
    }
    #pragma unroll
    for (int o = 16; o; o >>= 1) s += __shfl_xor_sync(0xffffffffu, s, o);
    return s;
}

// ---------------- K1: fused weight-convert + mean partials (independent work) ----
__global__ void __launch_bounds__(256) k_init(
    const float* __restrict__ W_in, const float* __restrict__ W_out,
    const float* __restrict__ xpf,  const float* __restrict__ xpb,
    const float* __restrict__ dtf,  const float* __restrict__ dtb_,
    const float* __restrict__ x,    __nv_bfloat16* __restrict__ wb)
{
    int b = blockIdx.x, tid = threadIdx.x;
    if (b < 6144){
        int i = b*256 + tid;                 // [0, 1572864)
        if (i < 2*DI*DM) wb[OFF_WIN + i] = __float2bfloat16(W_in[i]);
        else wb[OFF_WOUT + i - 2*DI*DM] = __float2bfloat16(W_out[i - 2*DI*DM]);
    } else if (b < 6912){
        int i = (b - 6144)*256 + tid;        // [0, 196608)
        if (i < 65536) wb[OFF_XPF + i] = __float2bfloat16(xpf[i]);
        else if (i < 131072) wb[OFF_XPB + i-65536] = __float2bfloat16(xpb[i-65536]);
        else if (i < 163840) wb[OFF_DTWF + i-131072] = __float2bfloat16(dtf[i-131072]);
        else wb[OFF_DTWB + i-163840] = __float2bfloat16(dtb_[i-163840]);
    } else {
        int idx = b - 6912;                  // [0, 128): mean partials
        int n = idx >> 3, p = idx & 7;
        const float* px = x + ((size_t)n*LL + p*64)*DM;
        for (int j = tid; j < DM; j += 256){
            float s = 0.f;
            #pragma unroll 8
            for (int t = 0; t < 64; t++) s += px[(size_t)t*DM + j];
            g_xmean_part[p][n*DM + j] = s;
        }
    }
}

// ---------------- conditioning (split, warp-per-output) ----------------
__global__ void __launch_bounds__(256) k_gf(const float* __restrict__ Wgf,
                                            const float* __restrict__ bgf){
    __shared__ __align__(16) float sx[DM];
    int n = blockIdx.x, tid = threadIdx.x;
    for (int k = tid; k < DM; k += 256){
        float s = 0.f;
        #pragma unroll
        for (int p = 0; p < 8; p++) s += g_xmean_part[p][n*DM + k];
        sx[k] = s * (1.0f/LL);
    }
    __syncthreads();
    int wid = tid >> 5, lane = tid & 31;
    int j = blockIdx.y*8 + wid;
    float s = warp_dot(Wgf + (size_t)j*DM, sx, DM, lane);
    if (lane == 0) g_gf[n*128 + j] = geluf(s + bgf[j]);
}
__global__ void __launch_bounds__(256) k_h1(const float* __restrict__ W1,
                                            const float* __restrict__ b1,
                                            const float* __restrict__ emb,
                                            const int* __restrict__ sid){
    __shared__ __align__(16) float sc[256];
    int n = blockIdx.x, tid = threadIdx.x;
    if (tid < 128) sc[tid] = g_gf[n*128 + tid];
    else sc[tid] = emb[sid[0]*128 + (tid-128)];
    __syncthreads();
    int wid = tid >> 5, lane = tid & 31;
    int j = blockIdx.y*8 + wid;
    float s = warp_dot(W1 + (size_t)j*256, sc, 256, lane);
    if (lane == 0) g_h1[n*DM + j] = geluf(s + b1[j]);
}
__global__ void __launch_bounds__(256) k_h2(const float* __restrict__ W2,
                                            const float* __restrict__ b2){
    __shared__ __align__(16) float sh[DM];
    int n = blockIdx.x, tid = threadIdx.x;
    for (int k = tid; k < DM; k += 256) sh[k] = g_h1[n*DM + k];
    __syncthreads();
    int wid = tid >> 5, lane = tid & 31;
    int j = blockIdx.y*8 + wid;
    float s = warp_dot(W2 + (size_t)j*DM, sh, DM, lane);
    if (lane == 0) g_h2[n*DM + j] = geluf(s + b2[j]);
}
__global__ void __launch_bounds__(256) k_offmm(const float* __restrict__ W3,
                                               const float* __restrict__ b3){
    __shared__ __align__(16) float sh[DM];
    int n = blockIdx.x, tid = threadIdx.x;
    for (int k = tid; k < DM; k += 256) sh[k] = g_h2[n*DM + k];
    __syncthreads();
    int wid = tid >> 5, lane = tid & 31;
    int j = blockIdx.y*8 + wid;
    float s = warp_dot(W3 + (size_t)j*DM, sh, DM, lane);
    if (lane == 0) g_off[n*1536 + j] = s + b3[j];
}
__global__ void k_offln(const float* __restrict__ lng, const float* __restrict__ lnb,
                        const int* __restrict__ sid){
    __shared__ float r1[16], r2[16];
    int n = blockIdx.x, c = blockIdx.y, j = threadIdx.x;
    float s = g_off[n*1536 + c*DM + j];
    float s1 = s, s2 = s*s;
    #pragma unroll
    for (int o = 16; o > 0; o >>= 1){
        s1 += __shfl_xor_sync(0xffffffffu, s1, o);
        s2 += __shfl_xor_sync(0xffffffffu, s2, o);
    }
    int wid = j >> 5, ln = j & 31;
    if (ln == 0){ r1[wid] = s1; r2[wid] = s2; }
    __syncthreads();
    if (j < 16){
        float a = r1[j], b = r2[j];
        #pragma unroll
        for (int o = 8; o > 0; o >>= 1){
            a += __shfl_xor_sync(0x0000ffffu, a, o);
            b += __shfl_xor_sync(0x0000ffffu, b, o);
        }
        if (j == 0){ r1[0] = a; r2[0] = b; }
    }
    __syncthreads();
    float mu  = r1[0] * (1.0f/DM);
    float var = r2[0] * (1.0f/DM) - mu*mu;
    float v = (s - mu) * rsqrtf(var + 1e-5f) * lng[j] + lnb[j];
    if (c == 0){
        float scv = 0.9f - 0.3f*(float)sid[0];
        g_dA[n*DM + j] = v * scv;
    } else if (c == 1) g_dB[n*DM + j] = v;
    else               g_dC[n*DM + j] = v;
}

// ---------------- residual + rmsnorm ----------------
__global__ void k_res(const float* __restrict__ x, const float* __restrict__ hinit,
                      const float* __restrict__ rmsw, float* __restrict__ resid){
    __shared__ float red[16];
    int m = blockIdx.x, j = threadIdx.x;
    int n = m >> 9, t = m & 511;
    float v = x[(size_t)m*DM + j] + g_dB[n*DM + j];
    if (t == 0) v += hinit[n*DM + j];
    resid[(size_t)m*DM + j] = v;
    float s2 = v*v;
    #pragma unroll
    for (int o = 16; o > 0; o >>= 1) s2 += __shfl_xor_sync(0xffffffffu, s2, o);
    int wid = j >> 5, ln = j & 31;
    if (ln == 0) red[wid] = s2;
    __syncthreads();
    if (j < 16){
        float a = red[j];
        #pragma unroll
        for (int o = 8; o > 0; o >>= 1) a += __shfl_xor_sync(0x0000ffffu, a, o);
        if (j == 0) red[0] = a;
    }
    __syncthreads();
    float rs = rsqrtf(red[0]*(1.0f/DM) + 1e-5f);
    g_hnb[(size_t)m*DM + j] = __float2bfloat16(v * rs * rmsw[j]);
}

// ---------------- bf16 GEMM, 2-stage cp.async, dynamic smem, dir-batched ---------
// EPI: 2 fp32 + bf16 copy col<32 (pitch DTR); 4 final fusion; 5 bf16 store;
//      6 softplus(+bias) -> bf16 store.
struct GemmArgs {
    const __nv_bfloat16* A;
    const __nv_bfloat16* B;
    float* C;
    __nv_bfloat16* Cb;
    const float* bias;
};
template<int BM,int BN,int BK,int WGM,int WGN,int EPI>
__global__ void __launch_bounds__(256) gemm_bf16(
    GemmArgs a0, GemmArgs a1,
    int lda, int ldb, int ldc, int K,
    const float* __restrict__ resid, const float* __restrict__ dAp,
    const float* __restrict__ dCp, const float* __restrict__ resw,
    float* __restrict__ hfin)
{
    constexpr int PITCH = BK + 8;
    constexpr int WM = BM/WGM, WN = BN/WGN;
    constexpr int MF = WM/16, NF = WN/8;
    extern __shared__ __align__(16) __nv_bfloat16 smem[];
    __nv_bfloat16* sA = smem;                       // [2][BM*PITCH]
    __nv_bfloat16* sB = smem + 2*BM*PITCH;          // [2][BN*PITCH]
    GemmArgs ga = (blockIdx.z == 0) ? a0 : a1;
    const __nv_bfloat16* A = ga.A;
    const __nv_bfloat16* B = ga.B;
    int tid = threadIdx.x;
    int lane = tid & 31, wid = tid >> 5;
    int wm = wid % WGM, wn = wid / WGM;
    int bm0 = blockIdx.y*BM, bn0 = blockIdx.x*BN;

    float acc[MF][NF][4];
    #pragma unroll
    for (int i = 0; i < MF; i++)
        #pragma unroll
        for (int j = 0; j < NF; j++)
            #pragma unroll
            for (int r = 0; r < 4; r++) acc[i][j][r] = 0.f;

    auto load_tile = [&](int st, int k0){
        constexpr int CA = BM*BK/8;
        __nv_bfloat16* dA_ = sA + st*BM*PITCH;
        #pragma unroll
        for (int c = tid; c < CA; c += 256){
            int r = c/(BK/8), c8 = c%(BK/8);
            const void* src = &A[(size_t)(bm0+r)*lda + k0 + c8*8];
            unsigned dst = (unsigned)__cvta_generic_to_shared(&dA_[r*PITCH + c8*8]);
            asm volatile("cp.async.cg.shared.global [%0], [%1], 16;" :: "r"(dst), "l"(src));
        }
        constexpr int CB = BN*BK/8;
        __nv_bfloat16* dB_ = sB + st*BN*PITCH;
        #pragma unroll
        for (int c = tid; c < CB; c += 256){
            int r = c/(BK/8), c8 = c%(BK/8);
            const void* src = &B[(size_t)(bn0+r)*ldb + k0 + c8*8];
            unsigned dst = (unsigned)__cvta_generic_to_shared(&dB_[r*PITCH + c8*8]);
            asm volatile("cp.async.cg.shared.global [%0], [%1], 16;" :: "r"(dst), "l"(src));
        }
    };

    const int KT = K / BK;
    load_tile(0, 0);
    asm volatile("cp.async.commit_group;");
    for (int kt = 0; kt < KT; kt++){
        if (kt + 1 < KT) load_tile((kt+1)&1, (kt+1)*BK);
        asm volatile("cp.async.commit_group;");
        asm volatile("cp.async.wait_group 1;");
        __syncthreads();
        int st = kt & 1;
        const __nv_bfloat16* tA = sA + st*BM*PITCH;
        const __nv_bfloat16* tB = sB + st*BN*PITCH;
        #pragma unroll
        for (int kc = 0; kc < BK; kc += 16){
            unsigned af[MF][4], bf[NF][2];
            #pragma unroll
            for (int mf = 0; mf < MF; mf++){
                unsigned addr = (unsigned)__cvta_generic_to_shared(
                    &tA[(wm*WM + mf*16 + (lane&15))*PITCH + kc + (lane>>4)*8]);
                asm volatile("ldmatrix.sync.aligned.m8n8.x4.shared.b16 {%0,%1,%2,%3}, [%4];"
                    : "=r"(af[mf][0]),"=r"(af[mf][1]),"=r"(af[mf][2]),"=r"(af[mf][3])
                    : "r"(addr));
            }
            #pragma unroll
            for (int nf = 0; nf < NF; nf++){
                unsigned addr = (unsigned)__cvta_generic_to_shared(
                    &tB[(wn*WN + nf*8 + (lane&7))*PITCH + kc + ((lane>>3)&1)*8]);
                asm volatile("ldmatrix.sync.aligned.m8n8.x2.shared.b16 {%0,%1}, [%2];"
                    : "=r"(bf[nf][0]),"=r"(bf[nf][1]) : "r"(addr));
            }
            #pragma unroll
            for (int mf = 0; mf < MF; mf++)
                #pragma unroll
                for (int nf = 0; nf < NF; nf++)
                    mma_bf16(acc[mf][nf], af[mf], bf[nf]);
        }
        __syncthreads();
    }

    float rw = 0.f;
    if (EPI == 4) rw = resw[0];
    #pragma unroll
    for (int mf = 0; mf < MF; mf++){
        int row0 = bm0 + wm*WM + mf*16 + (lane >> 2);
        #pragma unroll
        for (int nf = 0; nf < NF; nf++){
            int col = bn0 + wn*WN + nf*8 + (lane & 3)*2;
            float v[4] = {acc[mf][nf][0], acc[mf][nf][1], acc[mf][nf][2], acc[mf][nf][3]};
            if (EPI == 6){
                float bA = ga.bias[col], bB = ga.bias[col+1];
                v[0] = softplusf(v[0]+bA); v[1] = softplusf(v[1]+bB);
                v[2] = softplusf(v[2]+bA); v[3] = softplusf(v[3]+bB);
            }
            if (EPI == 4){
                #pragma unroll
                for (int h = 0; h < 2; h++){
                    int row = row0 + h*8;
                    int n = row >> 9, t = row & 511;
                    float A0 = 1.0f + 0.1f*dAp[n*DM + col];
                    float A1 = 1.0f + 0.1f*dAp[n*DM + col+1];
                    float c0 = 0.1f*dCp[n*DM + col];
                    float c1 = 0.1f*dCp[n*DM + col+1];
                    float r0 = rw*resid[(size_t)row*DM + col];
                    float r1 = rw*resid[(size_t)row*DM + col+1];
                    v[2*h]   = v[2*h]*A0 + c0 + r0;
                    v[2*h+1] = v[2*h+1]*A1 + c1 + r1;
                    if (t == LL-1){
                        hfin[n*DM + col]   = v[2*h];
                        hfin[n*DM + col+1] = v[2*h+1];
                    }
                }
            }
            if (EPI == 5 || EPI == 6){
                __nv_bfloat162 p0, p1;
                p0.x = __float2bfloat16(v[0]); p0.y = __float2bfloat16(v[1]);
                p1.x = __float2bfloat16(v[2]); p1.y = __float2bfloat16(v[3]);
                *(__nv_bfloat162*)&ga.Cb[(size_t)row0*ldc + col]     = p0;
                *(__nv_bfloat162*)&ga.Cb[(size_t)(row0+8)*ldc + col] = p1;
            } else {
                *(float2*)&ga.C[(size_t)row0*ldc + col]     = make_float2(v[0], v[1]);
                *(float2*)&ga.C[(size_t)(row0+8)*ldc + col] = make_float2(v[2], v[3]);
                if (EPI == 2 && col < 32){
                    ga.Cb[row0*DTR + col]       = __float2bfloat16(v[0]);
                    ga.Cb[row0*DTR + col+1]     = __float2bfloat16(v[1]);
                    ga.Cb[(row0+8)*DTR + col]   = __float2bfloat16(v[2]);
                    ga.Cb[(row0+8)*DTR + col+1] = __float2bfloat16(v[3]);
                }
            }
        }
    }
}

// ---------------- depthwise conv + silu, both dirs (blockIdx.z) ----------------
__global__ void k_conv(const float* __restrict__ cwf, const float* __restrict__ cbf,
                       const float* __restrict__ cwb, const float* __restrict__ cbb){
    int dir = blockIdx.z;
    const float* cw = dir ? cwb : cwf;
    const float* cb = dir ? cbb : cbf;
    int blk = blockIdx.x;                   // (NB*64, 4, 2) x 256
    int n = blk >> 6, tt = (blk & 63)*8;
    int d = blockIdx.y*256 + threadIdx.x;
    const float* w = cw + d*4;
    float w0 = w[0], w1 = w[1], w2 = w[2], w3 = w[3];
    float bias = cb[d];
    float xv[11];
    #pragma unroll
    for (int j = 0; j < 11; j++){
        int tau = tt - 3 + j;
        if (tau >= 0){
            int src = dir ? (LL-1-tau) : tau;
            xv[j] = __bfloat162float(g_xzb[(size_t)(n*LL + src)*(2*DI) + d]);
        } else xv[j] = 0.f;
    }
    __nv_bfloat16* dst = g_xcb2[dir];
    #pragma unroll
    for (int i = 0; i < 8; i++){
        float s = bias + w0*xv[i] + w1*xv[i+1] + w2*xv[i+2] + w3*xv[i+3];
        size_t m = (size_t)(n*LL + tt + i);
        dst[m*DI + d] = __float2bfloat16(siluf(s));
    }
}

// ---------------- selective scan, both dirs in one launch (blockIdx.z) ----------
__global__ void __launch_bounds__(256) k_scan2(
    const float* __restrict__ Af, const float* __restrict__ Df,
    const float* __restrict__ Ab, const float* __restrict__ Db)
{
    int dir = blockIdx.z;
    const float* Alog = dir ? Ab : Af;
    const float* Dp   = dir ? Db : Df;
    const __nv_bfloat16* xu  = g_xcb2[dir];
    const __nv_bfloat16* dtp = g_dtb2[dir];
    const float* dbl = g_dbl2[dir];
    __nv_bfloat16* y = g_yb2[dir];

    int n  = blockIdx.y;
    int ch = blockIdx.x*64 + (threadIdx.x >> 2);
    int s0 = (threadIdx.x & 3) * 4;
    bool lead = (threadIdx.x & 3) == 0;
    float A2[4];
    #pragma unroll
    for (int i = 0; i < 4; i++)
        A2[i] = -__expf(Alog[ch*DS + s0 + i]) * 1.44269504088896f;
    float Dv = Dp[ch];
    float h0=0.f,h1=0.f,h2=0.f,h3=0.f;
    size_t base = (size_t)n*LL;

    float pu[8], pd[8]; float4 pB[8], pC[8];
    #pragma unroll
    for (int i = 0; i < 8; i++){
        size_t r = base + i;
        pu[i] = __bfloat162float(xu[r*DI + ch]);
        pd[i] = __bfloat162float(dtp[r*DI + ch]);
        pB[i] = *(const float4*)&dbl[r*64 + DTR + s0];
        pC[i] = *(const float4*)&dbl[r*64 + DTR + DS + s0];
    }

    for (int t0 = 0; t0 < LL; t0 += 8){
        #pragma unroll
        for (int i = 0; i < 8; i++){
            int t = t0 + i;
            float u = pu[i], dv = pd[i];
            float4 Bv = pB[i], Cv = pC[i];
            int tn = t + 8;
            if (tn < LL){
                size_t r = base + tn;
                pu[i] = __bfloat162float(xu[r*DI + ch]);
                pd[i] = __bfloat162float(dtp[r*DI + ch]);
                pB[i] = *(const float4*)&dbl[r*64 + DTR + s0];
                pC[i] = *(const float4*)&dbl[r*64 + DTR + DS + s0];
            }
            float du = dv*u;
            h0 = exp2f(dv*A2[0])*h0 + du*Bv.x;
            h1 = exp2f(dv*A2[1])*h1 + du*Bv.y;
            h2 = exp2f(dv*A2[2])*h2 + du*Bv.z;
            h3 = exp2f(dv*A2[3])*h3 + du*Bv.w;
            float acc = h0*Cv.x + h1*Cv.y + h2*Cv.z + h3*Cv.w;
            acc += __shfl_xor_sync(0xffffffffu, acc, 1);
            acc += __shfl_xor_sync(0xffffffffu, acc, 2);
            if (lead){
                int tout = dir ? (LL-1-t) : t;
                y[(base + tout)*DI + ch] = __float2bfloat16(acc + u*Dv);
            }
        }
    }
}

// ---------------- ys = (y_f + y_b) * silu(z) -> bf16 ----------------
__global__ void k_ymul(){
    size_t m = blockIdx.x;
    int d = threadIdx.x*4;
    const __nv_bfloat162* y0p = (const __nv_bfloat162*)&g_yb2[0][m*DI + d];
    const __nv_bfloat162* y1p = (const __nv_bfloat162*)&g_yb2[1][m*DI + d];
    const __nv_bfloat162* zp  = (const __nv_bfloat162*)&g_xzb[m*(2*DI) + DI + d];
    __nv_bfloat162 o[2];
    #pragma unroll
    for (int q = 0; q < 2; q++){
        __nv_bfloat162 y0 = y0p[q], y1 = y1p[q], z = zp[q];
        float a = __bfloat162float(y0.x) + __bfloat162float(y1.x);
        float b = __bfloat162float(y0.y) + __bfloat162float(y1.y);
        o[q].x = __float2bfloat16(a * siluf(__bfloat162float(z.x)));
        o[q].y = __float2bfloat16(b * siluf(__bfloat162float(z.y)));
    }
    __nv_bfloat162* op = (__nv_bfloat162*)&g_xcb2[0][m*DI + d];
    op[0] = o[0]; op[1] = o[1];
}

// ---------------- launch ----------------
extern "C" void kernel_launch(void* const* d_in, const int* in_sizes, int n_in,
                              void* d_out, int out_size)
{
    const float* x      = (const float*)d_in[0];
    const int*   sid    = (const int*)  d_in[1];
    const float* h_init = (const float*)d_in[2];
    const float* W_gf   = (const float*)d_in[3];
    const float* b_gf   = (const float*)d_in[4];
    const float* emb    = (const float*)d_in[5];
    const float* W1     = (const float*)d_in[6];
    const float* b1     = (const float*)d_in[7];
    const float* W2     = (const float*)d_in[8];
    const float* b2     = (const float*)d_in[9];
    const float* W3     = (const float*)d_in[10];
    const float* b3     = (const float*)d_in[11];
    const float* ln_g   = (const float*)d_in[12];
    const float* ln_b   = (const float*)d_in[13];
    const float* rms_w  = (const float*)d_in[14];
    const float* W_in   = (const float*)d_in[15];
    const float* W_out  = (const float*)d_in[16];
    const float* res_w  = (const float*)d_in[17];
    const float* convw_f= (const float*)d_in[18];
    const float* convb_f= (const float*)d_in[19];
    const float* xproj_f= (const float*)d_in[20];
    const float* dtw_f  = (const float*)d_in[21];
    const float* dtb_f  = (const float*)d_in[22];
    const float* Alog_f = (const float*)d_in[23];
    const float* D_f    = (const float*)d_in[24];
    const float* convw_b= (const float*)d_in[25];
    const float* convb_b= (const float*)d_in[26];
    const float* xproj_b= (const float*)d_in[27];
    const float* dtw_b  = (const float*)d_in[28];
    const float* dtb_b  = (const float*)d_in[29];
    const float* Alog_b = (const float*)d_in[30];
    const float* D_b    = (const float*)d_in[31];

    float* out   = (float*)d_out;
    float* resid = out + (size_t)ROWS*DM;
    float* hfin  = out + 2*(size_t)ROWS*DM;

    float *p_dbl0, *p_dbl1, *p_dA, *p_dC;
    __nv_bfloat16 *p_hnb, *p_xzb, *p_xcb0, *p_xcb1, *p_dblb0, *p_dblb1, *p_dtb0, *p_dtb1, *p_wb;
    cudaGetSymbolAddress((void**)&p_dbl0, g_dbl2);
    p_dbl1 = p_dbl0 + (size_t)ROWS*64;
    cudaGetSymbolAddress((void**)&p_dA,   g_dA);
    cudaGetSymbolAddress((void**)&p_dC,   g_dC);
    cudaGetSymbolAddress((void**)&p_hnb,  g_hnb);
    cudaGetSymbolAddress((void**)&p_xzb,  g_xzb);
    cudaGetSymbolAddress((void**)&p_xcb0, g_xcb2);
    p_xcb1 = p_xcb0 + (size_t)ROWS*DI;
    cudaGetSymbolAddress((void**)&p_dblb0,g_dblb2);
    p_dblb1 = p_dblb0 + (size_t)ROWS*DTR;
    cudaGetSymbolAddress((void**)&p_dtb0, g_dtb2);
    p_dtb1 = p_dtb0 + (size_t)ROWS*DI;
    cudaGetSymbolAddress((void**)&p_wb,   g_wb);

    // dynamic smem sizes: 2*(BM+BN)*(BK+8)*2 bytes
    const int SM_BK64_128 = 2*(128+128)*72*2;  // 73728
    const int SM_BK64_64  = 2*(64+64)*72*2;    // 36864
    const int SM_BK32_128 = 2*(128+128)*40*2;  // 40960
    cudaFuncSetAttribute(gemm_bf16<128,128,64,2,4,5>,
        cudaFuncAttributeMaxDynamicSharedMemorySize, SM_BK64_128);
    cudaFuncSetAttribute(gemm_bf16<128,128,64,2,4,4>,
        cudaFuncAttributeMaxDynamicSharedMemorySize, SM_BK64_128);

    // (1) fused convert + mean partials
    k_init<<<7040, 256>>>(W_in, W_out, xproj_f, xproj_b, dtw_f, dtw_b, x, p_wb);

    // conditioning (split warp-per-output)
    k_gf<<<dim3(NB,16), 256>>>(W_gf, b_gf);
    k_h1<<<dim3(NB,64), 256>>>(W1, b1, emb, sid);
    k_h2<<<dim3(NB,64), 256>>>(W2, b2);
    k_offmm<<<dim3(NB,192), 256>>>(W3, b3);
    k_offln<<<dim3(NB,3), DM>>>(ln_g, ln_b, sid);

    // residual + rmsnorm
    k_res<<<ROWS, DM>>>(x, h_init, rms_w, resid);

    // xz = hn @ W_in.T -> bf16  (BK=64)
    {
        GemmArgs a0 = { p_hnb, p_wb + OFF_WIN, nullptr, p_xzb, nullptr };
        gemm_bf16<128,128,64,2,4,5><<<dim3(16, 64, 1), 256, SM_BK64_128>>>(
            a0, a0, DM, DM, 2*DI, DM, nullptr, nullptr, nullptr, nullptr, nullptr);
    }

    // conv both dirs
    k_conv<<<dim3(NB*64, 4, 2), 256>>>(convw_f, convb_f, convw_b, convb_b);

    // xproj both dirs (fp32 B/C + bf16 dtraw), BK=64
    {
        GemmArgs a0 = { p_xcb0, p_wb + OFF_XPF, p_dbl0, p_dblb0, nullptr };
        GemmArgs a1 = { p_xcb1, p_wb + OFF_XPB, p_dbl1, p_dblb1, nullptr };
        gemm_bf16<64,64,64,2,4,2><<<dim3(1, 128, 2), 256, SM_BK64_64>>>(
            a0, a1, DI, DI, 64, DI, nullptr, nullptr, nullptr, nullptr, nullptr);
    }

    // dt both dirs -> softplus -> bf16 (K=32, single tile, BK=32)
    {
        GemmArgs a0 = { p_dblb0, p_wb + OFF_DTWF, nullptr, p_dtb0, dtb_f };
        GemmArgs a1 = { p_dblb1, p_wb + OFF_DTWB, nullptr, p_dtb1, dtb_b };
        gemm_bf16<128,128,32,2,4,6><<<dim3(8, 64, 2), 256, SM_BK32_128>>>(
            a0, a1, DTR, DTR, DI, DTR, nullptr, nullptr, nullptr, nullptr, nullptr);
    }

    // scan both dirs concurrently
    k_scan2<<<dim3(16, NB, 2), 256>>>(Alog_f, D_f, Alog_b, D_b);

    // gating
    k_ymul<<<ROWS, 256>>>();

    // W_out gemm with fused final epilogue  (BK=64)
    {
        GemmArgs a0 = { p_xcb0, p_wb + OFF_WOUT, out, nullptr, nullptr };
        gemm_bf16<128,128,64,2,4,4><<<dim3(4, 64, 1), 256, SM_BK64_128>>>(
            a0, a0, DI, DI, DM, DI, resid, p_dA, p_dC, res_w, hfin);
    }
}